// round 9
// baseline (speedup 1.0000x reference)
#include <cuda_runtime.h>
#include <math.h>

#define VOC      50257
#define EMB      128
#define N_MEM    8192
#define T_Q      50
#define T_M      50
#define N_HOPS   3

#define NBS   444               // stream blocks (3/SM)
#define TBS   256
#define WPB   8

#define SROWS 8                 // rows per pipeline stage (4 KB)
#define NSTG  8                 // ring depth (32 KB smem)

#define STG_V ((VOC + SROWS - 1) / SROWS)     // 6283 vocab stages
#define SPB_V ((STG_V + NBS - 1) / NBS)       // 15 per block
#define STG_M (N_MEM / SROWS)                 // 1024 memory stages
#define SPB_M ((STG_M + NBS - 1) / NBS)       // 3 per block

#define NBM  128                 // memory-space kernel
#define TBM  64

#define SHIFT 24.0f              // constant softmax shift (cancels exactly)
#define NEGBIG (-1e30f)

// ---------------- scratch ----------------
__device__ __align__(16) float g_u[EMB];
__device__ __align__(16) float g_pv[VOC + 8];
__device__ __align__(16) float g_sTA[N_MEM];
__device__ __align__(16) float g_cw[VOC + 8];
__device__ __align__(16) float g_wo[EMB];
__device__ float g_den;
__device__ float g_plmax[NBS];
__device__ float g_plden[NBS];

__device__ __forceinline__ float dot4(float4 a, float4 b) {
    return fmaf(a.x, b.x, fmaf(a.y, b.y, fmaf(a.z, b.z, a.w * b.w)));
}
__device__ __forceinline__ float warp_sum(float p) {
#pragma unroll
    for (int o = 16; o; o >>= 1) p += __shfl_xor_sync(0xFFFFFFFFu, p, o);
    return p;
}

// issue one stage: 256 threads x 16B cp.async = 8 rows of 512B
__device__ __forceinline__ void stage_issue(const float* __restrict__ W,
                                            long row0, long nrows,
                                            unsigned sdst) {
    int t = threadIdx.x;
    long row = row0 + (t >> 5);
    if (row >= nrows) row = nrows - 1;           // clamp (consumer guards output)
    const float* src = W + row * EMB + (t & 31) * 4;
    asm volatile("cp.async.cg.shared.global [%0], [%1], 16;\n"
                 :: "r"(sdst + (unsigned)t * 16), "l"(src));
    asm volatile("cp.async.commit_group;\n");
}
#define PIPE_WAIT(cond) do { \
    if (cond) asm volatile("cp.async.wait_group 6;\n"); \
    else      asm volatile("cp.async.wait_group 0;\n"); \
} while (0)

// ---------------- u0 = sum_t Wb[query[t]] ----------------
__global__ void k_u0(const int* __restrict__ q, const float* __restrict__ Wb) {
    int e = threadIdx.x;
    float a = 0.f;
#pragma unroll 10
    for (int t = 0; t < T_Q; t++) a += Wb[(long)__ldg(q + t) * EMB + e];
    g_u[e] = a;
}

// ---------------- pv = Wa.u ; sTA = TA.u ; zero cw/wo/den ----------------
__global__ void __launch_bounds__(TBS) k_pv(const float* __restrict__ Wa,
                                            const float* __restrict__ TA) {
    __shared__ __align__(16) float ring[NSTG][SROWS][EMB];   // 32 KB
    __shared__ float4 su4[32];
    int tid = threadIdx.x, lane = tid & 31, wid = tid >> 5;
    unsigned sring = (unsigned)__cvta_generic_to_shared(ring);

    int gid = blockIdx.x * TBS + tid;
    if (gid < VOC) g_cw[gid] = 0.f;
    if (blockIdx.x == 0) {
        if (tid < EMB) g_wo[tid] = 0.f;
        if (tid == EMB) g_den = 0.f;
    }
    if (tid < 32) su4[tid] = ((const float4*)g_u)[tid];
    __syncthreads();
    float4 uu = su4[lane];

    // ---- pipeline 1: Wa -> g_pv ----
    {
        int sb = blockIdx.x * SPB_V;
        int ns = STG_V - sb; ns = ns < 0 ? 0 : (ns > SPB_V ? SPB_V : ns);
        for (int i = 0; i < NSTG - 1 && i < ns; i++)
            stage_issue(Wa, (long)(sb + i) * SROWS, VOC, sring + (i % NSTG) * (SROWS * EMB * 4));
        for (int s = 0; s < ns; s++) {
            bool more = (s + NSTG - 1 < ns);
            if (more)
                stage_issue(Wa, (long)(sb + s + NSTG - 1) * SROWS, VOC,
                            sring + ((s + NSTG - 1) % NSTG) * (SROWS * EMB * 4));
            PIPE_WAIT(more);
            __syncthreads();
            long row = (long)(sb + s) * SROWS + wid;
            float4 v = ((const float4*)ring[s % NSTG][wid])[lane];
            float p = warp_sum(dot4(v, uu));
            if (lane == 0 && row < VOC) g_pv[row] = p;
            __syncthreads();
        }
    }
    // ---- pipeline 2: TA -> g_sTA ----
    {
        int sb = blockIdx.x * SPB_M;
        int ns = STG_M - sb; ns = ns < 0 ? 0 : (ns > SPB_M ? SPB_M : ns);
        for (int i = 0; i < NSTG - 1 && i < ns; i++)
            stage_issue(TA, (long)(sb + i) * SROWS, N_MEM, sring + (i % NSTG) * (SROWS * EMB * 4));
        for (int s = 0; s < ns; s++) {
            bool more = (s + NSTG - 1 < ns);
            if (more)
                stage_issue(TA, (long)(sb + s + NSTG - 1) * SROWS, N_MEM,
                            sring + ((s + NSTG - 1) % NSTG) * (SROWS * EMB * 4));
            PIPE_WAIT(more);
            __syncthreads();
            long row = (long)(sb + s) * SROWS + wid;
            float4 v = ((const float4*)ring[s % NSTG][wid])[lane];
            float p = warp_sum(dot4(v, uu));
            if (lane == 0 && row < N_MEM) g_sTA[row] = p;
            __syncthreads();
        }
    }
}

// ---------------- per-memory: score gather, w=exp, denom, scatter cw, w*TC ----------------
__global__ void k_hopmem(const int* __restrict__ story, const float* __restrict__ TC) {
    __shared__ int   sst[TBM * T_M];
    __shared__ float sw[TBM];
    __shared__ float sred[TBM / 32];
    __shared__ float sacc[TBM / 32][EMB];
    int tid = threadIdx.x, lane = tid & 31, wid = tid >> 5;

    long base = (long)blockIdx.x * TBM * T_M;
#pragma unroll 4
    for (int i = tid; i < TBM * T_M; i += TBM) sst[i] = story[base + i];
    __syncthreads();

    int n = blockIdx.x * TBM + tid;
    float s = g_sTA[n];
#pragma unroll 10
    for (int t = 0; t < T_M; t++) s += g_pv[sst[tid * T_M + t]];
    float w = __expf(s - SHIFT);
    sw[tid] = w;

    float d = warp_sum(w);
    if (lane == 0) sred[wid] = d;

#pragma unroll 10
    for (int t = 0; t < T_M; t++) atomicAdd(&g_cw[sst[tid * T_M + t]], w);
    __syncthreads();

    if (tid == 0) {
        float db = 0.f;
#pragma unroll
        for (int i = 0; i < TBM / 32; i++) db += sred[i];
        atomicAdd(&g_den, db);
    }

    float4 acc = make_float4(0.f, 0.f, 0.f, 0.f);
    for (int j = wid; j < TBM; j += TBM / 32) {
        float wn = sw[j];
        float4 v = ((const float4*)(TC + (long)(blockIdx.x * TBM + j) * EMB))[lane];
        acc.x += wn * v.x; acc.y += wn * v.y; acc.z += wn * v.z; acc.w += wn * v.w;
    }
    sacc[wid][lane * 4 + 0] = acc.x;
    sacc[wid][lane * 4 + 1] = acc.y;
    sacc[wid][lane * 4 + 2] = acc.z;
    sacc[wid][lane * 4 + 3] = acc.w;
    __syncthreads();
    if (tid < EMB / 2) {
#pragma unroll
        for (int k = 0; k < 2; k++) {
            int e = tid * 2 + k;
            float v = 0.f;
#pragma unroll
            for (int w2 = 0; w2 < TBM / 32; w2++) v += sacc[w2][e];
            atomicAdd(&g_wo[e], v);
        }
    }
}

// ---------------- wo += Wc^T.cw (pipelined; no shuffles) ----------------
__global__ void __launch_bounds__(TBS) k_wo(const float* __restrict__ Wc) {
    __shared__ __align__(16) float ring[NSTG][SROWS][EMB];   // 32 KB
    __shared__ float sacc[WPB][EMB];                          // 4 KB
    int tid = threadIdx.x, lane = tid & 31, wid = tid >> 5;
    unsigned sring = (unsigned)__cvta_generic_to_shared(ring);

    int sb = blockIdx.x * SPB_V;
    int ns = STG_V - sb; ns = ns < 0 ? 0 : (ns > SPB_V ? SPB_V : ns);

    float4 acc = make_float4(0.f, 0.f, 0.f, 0.f);
    for (int i = 0; i < NSTG - 1 && i < ns; i++)
        stage_issue(Wc, (long)(sb + i) * SROWS, VOC, sring + (i % NSTG) * (SROWS * EMB * 4));
    for (int s = 0; s < ns; s++) {
        bool more = (s + NSTG - 1 < ns);
        if (more)
            stage_issue(Wc, (long)(sb + s + NSTG - 1) * SROWS, VOC,
                        sring + ((s + NSTG - 1) % NSTG) * (SROWS * EMB * 4));
        PIPE_WAIT(more);
        __syncthreads();
        long row = (long)(sb + s) * SROWS + wid;
        float c = (row < VOC) ? g_cw[row] : 0.f;     // warp-uniform broadcast
        float4 v = ((const float4*)ring[s % NSTG][wid])[lane];
        acc.x = fmaf(c, v.x, acc.x);
        acc.y = fmaf(c, v.y, acc.y);
        acc.z = fmaf(c, v.z, acc.z);
        acc.w = fmaf(c, v.w, acc.w);
        __syncthreads();
    }
    sacc[wid][lane * 4 + 0] = acc.x;
    sacc[wid][lane * 4 + 1] = acc.y;
    sacc[wid][lane * 4 + 2] = acc.z;
    sacc[wid][lane * 4 + 3] = acc.w;
    __syncthreads();
    if (tid < EMB) {
        float v = 0.f;
#pragma unroll
        for (int w2 = 0; w2 < WPB; w2++) v += sacc[w2][tid];
        if (v != 0.f) atomicAdd(&g_wo[tid], v);
    }
}

// ---------------- gated update of u ----------------
__global__ void k_update(const float* __restrict__ Wt_w, const float* __restrict__ Wt_b,
                         const float* __restrict__ H_w,  const float* __restrict__ H_b) {
    __shared__ __align__(16) float su[EMB], swo[EMB], sdt[EMB], sdh[EMB];
    int tid = threadIdx.x, lane = tid & 31, wid = tid >> 5;
    if (tid < EMB) {
        su[tid]  = g_u[tid];
        swo[tid] = g_wo[tid] / g_den;
    }
    __syncthreads();

    const float* W   = (wid < 4) ? Wt_w : H_w;
    const float* vec = (wid < 4) ? su : swo;
    float*       dst = (wid < 4) ? sdt : sdh;
    float4 v4 = ((const float4*)vec)[lane];
    int r0 = (wid & 3) * 32;
#pragma unroll 4
    for (int j = 0; j < 32; j++) {
        int row = r0 + j;
        float4 w4 = ((const float4*)(W + (long)row * EMB))[lane];
        float p = warp_sum(dot4(w4, v4));
        if (lane == 0) dst[row] = p;
    }
    __syncthreads();
    if (tid < EMB) {
        float t = 1.f / (1.f + __expf(-(sdt[tid] + Wt_b[tid])));
        g_u[tid] = su[tid] * (1.f - t) + (sdh[tid] + H_b[tid]) * t;
    }
}

// ---------------- logits + online partials (pipelined) ----------------
__global__ void __launch_bounds__(TBS) k_logits(const float* __restrict__ wout,
                                                float* __restrict__ out) {
    __shared__ __align__(16) float ring[NSTG][SROWS][EMB];   // 32 KB
    __shared__ float4 su4[32];
    __shared__ float sm[WPB], sd[WPB];
    int tid = threadIdx.x, lane = tid & 31, wid = tid >> 5;
    unsigned sring = (unsigned)__cvta_generic_to_shared(ring);

    if (tid < 32) su4[tid] = ((const float4*)g_u)[tid];
    __syncthreads();
    float4 uu = su4[lane];

    int sb = blockIdx.x * SPB_V;
    int ns = STG_V - sb; ns = ns < 0 ? 0 : (ns > SPB_V ? SPB_V : ns);

    float m = NEGBIG, d = 0.f;
    for (int i = 0; i < NSTG - 1 && i < ns; i++)
        stage_issue(wout, (long)(sb + i) * SROWS, VOC, sring + (i % NSTG) * (SROWS * EMB * 4));
    for (int s = 0; s < ns; s++) {
        bool more = (s + NSTG - 1 < ns);
        if (more)
            stage_issue(wout, (long)(sb + s + NSTG - 1) * SROWS, VOC,
                        sring + ((s + NSTG - 1) % NSTG) * (SROWS * EMB * 4));
        PIPE_WAIT(more);
        __syncthreads();
        long row = (long)(sb + s) * SROWS + wid;
        float4 v = ((const float4*)ring[s % NSTG][wid])[lane];
        float p = warp_sum(dot4(v, uu));
        if (row < VOC) {
            if (lane == 0) out[row] = p;
            float mn = fmaxf(m, p);
            d = d * __expf(m - mn) + __expf(p - mn);
            m = mn;
        }
        __syncthreads();
    }
    if (lane == 0) { sm[wid] = m; sd[wid] = d; }
    __syncthreads();
    if (tid < 32) {
        float mm = (tid < WPB) ? sm[tid] : NEGBIG;
        float dd = (tid < WPB) ? sd[tid] : 0.f;
#pragma unroll
        for (int o = 4; o; o >>= 1) {
            float mo  = __shfl_xor_sync(0xFFFFFFFFu, mm, o);
            float ddo = __shfl_xor_sync(0xFFFFFFFFu, dd, o);
            float mn  = fmaxf(mm, mo);
            dd = dd * __expf(mm - mn) + ddo * __expf(mo - mn);
            mm = mn;
        }
        if (tid == 0) { g_plmax[blockIdx.x] = mm; g_plden[blockIdx.x] = dd; }
    }
}

// ---------------- combine partials + normalize ----------------
__global__ void k_norm(float* __restrict__ out) {
    __shared__ float sc;
    int tid = threadIdx.x, lane = tid & 31;
    if (tid < 32) {
        float mm = NEGBIG, dd = 0.f;
        for (int b = lane; b < NBS; b += 32) {
            float mo = g_plmax[b], ddo = g_plden[b];
            float mn = fmaxf(mm, mo);
            dd = dd * __expf(mm - mn) + ddo * __expf(mo - mn);
            mm = mn;
        }
#pragma unroll
        for (int o = 16; o; o >>= 1) {
            float mo  = __shfl_xor_sync(0xFFFFFFFFu, mm, o);
            float ddo = __shfl_xor_sync(0xFFFFFFFFu, dd, o);
            float mn  = fmaxf(mm, mo);
            dd = dd * __expf(mm - mn) + ddo * __expf(mo - mn);
            mm = mn;
        }
        if (tid == 0) sc = mm + logf(dd);
    }
    __syncthreads();
    float c = sc;
    for (int i = blockIdx.x * blockDim.x + tid; i < VOC; i += gridDim.x * blockDim.x)
        out[i] -= c;
}

// ---------------- launch ----------------
extern "C" void kernel_launch(void* const* d_in, const int* in_sizes, int n_in,
                              void* d_out, int out_size) {
    const int*   query = (const int*)  d_in[0];
    const int*   story = (const int*)  d_in[1];
    const float* Wa    = (const float*)d_in[2];
    const float* Wc    = (const float*)d_in[3];
    const float* Wb    = (const float*)d_in[4];
    const float* Wt_w  = (const float*)d_in[5];
    const float* Wt_b  = (const float*)d_in[6];
    const float* H_w   = (const float*)d_in[7];
    const float* H_b   = (const float*)d_in[8];
    const float* wout  = (const float*)d_in[9];
    const float* TA    = (const float*)d_in[10];
    const float* TC    = (const float*)d_in[11];
    float* out = (float*)d_out;

    k_u0<<<1, EMB>>>(query, Wb);

    for (int h = 0; h < N_HOPS; h++) {
        k_pv    <<<NBS, TBS>>>(Wa, TA);
        k_hopmem<<<NBM, TBM>>>(story, TC);
        k_wo    <<<NBS, TBS>>>(Wc);
        k_update<<<1, 256>>>(Wt_w, Wt_b, H_w, H_b);
    }

    k_logits<<<NBS, TBS>>>(wout, out);
    k_norm  <<<148, 256>>>(out);
}

// round 10
// speedup vs baseline: 1.0981x; 1.0981x over previous
#include <cuda_runtime.h>
#include <math.h>

#define VOC      50257
#define VOC_BULK 50256           // divisible by 8
#define OCT_V    (VOC_BULK / 8)  // 6282 vocab row-octets
#define EMB      128
#define N_MEM    8192
#define OCT_M    (N_MEM / 8)     // 1024 memory row-octets
#define T_Q      50
#define T_M      50
#define N_HOPS   3

#define TBV  256
#define WPB  8
#define NB_PV ((OCT_V + OCT_M + 1 + WPB - 1) / WPB)   // 914 blocks (incl. tail warp)
#define NB_WO ((OCT_V + 1 + WPB - 1) / WPB)           // 786 blocks
#define NB_LG NB_WO

#define NBM  128                 // memory-space kernel
#define TBM  64

#define SHIFT 24.0f              // constant softmax shift (cancels exactly)
#define NEGBIG (-1e30f)

// ---------------- scratch ----------------
__device__ __align__(16) float g_u[EMB];
__device__ __align__(16) float g_pv[VOC + 8];
__device__ __align__(16) float g_sTA[N_MEM];
__device__ __align__(16) float g_cw[VOC + 8];
__device__ __align__(16) float g_wo[EMB];
__device__ float g_den;
__device__ float g_plmax[NB_LG];
__device__ float g_plden[NB_LG];
__device__ unsigned g_ctr_wo;
__device__ unsigned g_ctr_lg;

__device__ __forceinline__ float dot4(float4 a, float4 b) {
    return fmaf(a.x, b.x, fmaf(a.y, b.y, fmaf(a.z, b.z, a.w * b.w)));
}
__device__ __forceinline__ float warp_sum(float p) {
#pragma unroll
    for (int o = 16; o; o >>= 1) p += __shfl_xor_sync(0xFFFFFFFFu, p, o);
    return p;
}
__device__ __forceinline__ void oct_reduce(float* p) {
#pragma unroll
    for (int o = 16; o; o >>= 1) {
#pragma unroll
        for (int j = 0; j < 8; j++)
            p[j] += __shfl_xor_sync(0xFFFFFFFFu, p[j], o);
    }
}

// ---------------- u0 = sum_t Wb[query[t]] ----------------
__global__ void k_u0(const int* __restrict__ q, const float* __restrict__ Wb) {
    int e = threadIdx.x;
    float a = 0.f;
#pragma unroll 10
    for (int t = 0; t < T_Q; t++) a += Wb[(long)__ldg(q + t) * EMB + e];
    g_u[e] = a;
}

// ---------------- pv = Wa.u ; sTA = TA.u ; zero cw/wo/den (one octet per warp) ----------------
__global__ void __launch_bounds__(TBV) k_pv(const float* __restrict__ Wa,
                                            const float* __restrict__ TA) {
    __shared__ float4 su4[32];
    int tid = threadIdx.x, lane = tid & 31, wid = tid >> 5;
    int gid = blockIdx.x * TBV + tid;
    if (gid < VOC) g_cw[gid] = 0.f;
    if (blockIdx.x == 0) {
        if (tid < EMB) g_wo[tid] = 0.f;
        if (tid == EMB) g_den = 0.f;
    }
    if (tid < 32) su4[tid] = ((const float4*)g_u)[tid];
    __syncthreads();
    float4 uu = su4[lane];
    int gw = blockIdx.x * WPB + wid;

    if (gw < OCT_V) {
        const float4* a = (const float4*)(Wa + (long)gw * 8 * EMB);
        float4 v[8];
#pragma unroll
        for (int j = 0; j < 8; j++) v[j] = a[j * 32 + lane];
        float p[8];
#pragma unroll
        for (int j = 0; j < 8; j++) p[j] = dot4(v[j], uu);
        oct_reduce(p);
        if (lane == 0) {
            float4* dst = (float4*)(g_pv + gw * 8);
            dst[0] = make_float4(p[0], p[1], p[2], p[3]);
            dst[1] = make_float4(p[4], p[5], p[6], p[7]);
        }
    } else if (gw < OCT_V + OCT_M) {
        int oc = gw - OCT_V;
        const float4* a = (const float4*)(TA + (long)oc * 8 * EMB);
        float4 v[8];
#pragma unroll
        for (int j = 0; j < 8; j++) v[j] = a[j * 32 + lane];
        float p[8];
#pragma unroll
        for (int j = 0; j < 8; j++) p[j] = dot4(v[j], uu);
        oct_reduce(p);
        if (lane == 0) {
            float4* dst = (float4*)(g_sTA + oc * 8);
            dst[0] = make_float4(p[0], p[1], p[2], p[3]);
            dst[1] = make_float4(p[4], p[5], p[6], p[7]);
        }
    } else if (gw == OCT_V + OCT_M) {   // vocab tail row
        float p = warp_sum(dot4(((const float4*)(Wa + (long)VOC_BULK * EMB))[lane], uu));
        if (lane == 0) g_pv[VOC_BULK] = p;
    }
}

// ---------------- per-memory: score gather, w=exp, denom, scatter cw, w*TC ----------------
__global__ void k_hopmem(const int* __restrict__ story, const float* __restrict__ TC) {
    __shared__ int   sst[TBM * T_M];
    __shared__ float sw[TBM];
    __shared__ float sred[TBM / 32];
    __shared__ float sacc[TBM / 32][EMB];
    int tid = threadIdx.x, lane = tid & 31, wid = tid >> 5;

    long base = (long)blockIdx.x * TBM * T_M;
#pragma unroll 4
    for (int i = tid; i < TBM * T_M; i += TBM) sst[i] = story[base + i];
    __syncthreads();

    int n = blockIdx.x * TBM + tid;
    float s = g_sTA[n];
#pragma unroll 10
    for (int t = 0; t < T_M; t++) s += g_pv[sst[tid * T_M + t]];
    float w = __expf(s - SHIFT);
    sw[tid] = w;

    float d = warp_sum(w);
    if (lane == 0) sred[wid] = d;

#pragma unroll 10
    for (int t = 0; t < T_M; t++) atomicAdd(&g_cw[sst[tid * T_M + t]], w);
    __syncthreads();

    if (tid == 0) {
        float db = 0.f;
#pragma unroll
        for (int i = 0; i < TBM / 32; i++) db += sred[i];
        atomicAdd(&g_den, db);
    }

    float4 acc = make_float4(0.f, 0.f, 0.f, 0.f);
    for (int j = wid; j < TBM; j += TBM / 32) {
        float wn = sw[j];
        float4 v = ((const float4*)(TC + (long)(blockIdx.x * TBM + j) * EMB))[lane];
        acc.x += wn * v.x; acc.y += wn * v.y; acc.z += wn * v.z; acc.w += wn * v.w;
    }
    sacc[wid][lane * 4 + 0] = acc.x;
    sacc[wid][lane * 4 + 1] = acc.y;
    sacc[wid][lane * 4 + 2] = acc.z;
    sacc[wid][lane * 4 + 3] = acc.w;
    __syncthreads();
    if (tid < EMB / 2) {
#pragma unroll
        for (int k = 0; k < 2; k++) {
            int e = tid * 2 + k;
            float v = 0.f;
#pragma unroll
            for (int w2 = 0; w2 < TBM / 32; w2++) v += sacc[w2][e];
            atomicAdd(&g_wo[e], v);
        }
    }
}

// ---------------- wo += Wc^T.cw (one octet/warp); last block: gated update ----------------
__global__ void __launch_bounds__(TBV) k_wo(const float* __restrict__ Wc,
                     const float* __restrict__ Wt_w, const float* __restrict__ Wt_b,
                     const float* __restrict__ H_w,  const float* __restrict__ H_b) {
    __shared__ float sacc[WPB][EMB];
    __shared__ int slast;
    int tid = threadIdx.x, lane = tid & 31, wid = tid >> 5;
    int gw = blockIdx.x * WPB + wid;

    float4 acc = make_float4(0.f, 0.f, 0.f, 0.f);
    if (gw < OCT_V) {
        const float4* a = (const float4*)(Wc + (long)gw * 8 * EMB);
        float4 c4a = ((const float4*)g_cw)[gw * 2 + 0];
        float4 c4b = ((const float4*)g_cw)[gw * 2 + 1];
        float4 v[8];
#pragma unroll
        for (int j = 0; j < 8; j++) v[j] = a[j * 32 + lane];
        float c[8] = {c4a.x, c4a.y, c4a.z, c4a.w, c4b.x, c4b.y, c4b.z, c4b.w};
#pragma unroll
        for (int j = 0; j < 8; j++) {
            acc.x = fmaf(c[j], v[j].x, acc.x);
            acc.y = fmaf(c[j], v[j].y, acc.y);
            acc.z = fmaf(c[j], v[j].z, acc.z);
            acc.w = fmaf(c[j], v[j].w, acc.w);
        }
    } else if (gw == OCT_V) {   // tail row
        float c = g_cw[VOC_BULK];
        float4 v = ((const float4*)(Wc + (long)VOC_BULK * EMB))[lane];
        acc.x = c * v.x; acc.y = c * v.y; acc.z = c * v.z; acc.w = c * v.w;
    }
    sacc[wid][lane * 4 + 0] = acc.x;
    sacc[wid][lane * 4 + 1] = acc.y;
    sacc[wid][lane * 4 + 2] = acc.z;
    sacc[wid][lane * 4 + 3] = acc.w;
    __syncthreads();
    if (tid < EMB) {
        float v = 0.f;
#pragma unroll
        for (int w2 = 0; w2 < WPB; w2++) v += sacc[w2][tid];
        atomicAdd(&g_wo[tid], v);
    }
    __threadfence();
    if (tid == 0) slast = (atomicAdd(&g_ctr_wo, 1u) == (unsigned)(gridDim.x - 1));
    __syncthreads();
    if (!slast) return;

    // ---- last block: gated update (8 warps x 4 octet-rounds = 256 row-dots) ----
    __shared__ __align__(16) float su[EMB], swo[EMB], sdd[2 * EMB];
    if (tid < EMB) {
        su[tid]  = g_u[tid];
        swo[tid] = g_wo[tid] / g_den;
    }
    __syncthreads();
    {
        const float* W   = (wid < 4) ? Wt_w : H_w;            // uniform per warp
        const float* vec = (wid < 4) ? su : swo;
        float4 v4 = ((const float4*)vec)[lane];
        int base = (wid & 3) * 32;                            // row offset within matrix
#pragma unroll
        for (int r = 0; r < 4; r++) {
            int rr0 = base + r * 8;
            float4 w4[8];
#pragma unroll
            for (int j = 0; j < 8; j++)
                w4[j] = ((const float4*)(W + (long)(rr0 + j) * EMB))[lane];
            float p[8];
#pragma unroll
            for (int j = 0; j < 8; j++) p[j] = dot4(w4[j], v4);
            oct_reduce(p);
            if (lane < 8) sdd[((wid < 4) ? 0 : EMB) + rr0 + lane] = p[lane];
        }
    }
    __syncthreads();
    if (tid < EMB) {
        float t = 1.f / (1.f + __expf(-(sdd[tid] + Wt_b[tid])));
        g_u[tid] = su[tid] * (1.f - t) + (sdd[EMB + tid] + H_b[tid]) * t;
    }
    if (tid == 0) g_ctr_wo = 0u;
}

// ---------------- logits + online partials; last block combines + normalizes ----------------
__global__ void __launch_bounds__(TBV) k_logits(const float* __restrict__ wout,
                                                float* __restrict__ out) {
    __shared__ float4 su4[32];
    __shared__ float sm[WPB], sd[WPB];
    __shared__ float smm[TBV / 32], sdm[TBV / 32];
    __shared__ int slast;
    __shared__ float sc;
    int tid = threadIdx.x, lane = tid & 31, wid = tid >> 5;
    if (tid < 32) su4[tid] = ((const float4*)g_u)[tid];
    __syncthreads();
    float4 uu = su4[lane];
    int gw = blockIdx.x * WPB + wid;

    float m = NEGBIG, d = 0.f;
    if (gw < OCT_V) {
        const float4* a = (const float4*)(wout + (long)gw * 8 * EMB);
        float4 v[8];
#pragma unroll
        for (int j = 0; j < 8; j++) v[j] = a[j * 32 + lane];
        float p[8];
#pragma unroll
        for (int j = 0; j < 8; j++) p[j] = dot4(v[j], uu);
        oct_reduce(p);
        if (lane == 0) {
            float4* dst = (float4*)(out + gw * 8);
            dst[0] = make_float4(p[0], p[1], p[2], p[3]);
            dst[1] = make_float4(p[4], p[5], p[6], p[7]);
        }
        float mx = p[0];
#pragma unroll
        for (int j = 1; j < 8; j++) mx = fmaxf(mx, p[j]);
        m = mx; d = 0.f;
#pragma unroll
        for (int j = 0; j < 8; j++) d += __expf(p[j] - m);
    } else if (gw == OCT_V) {   // tail row
        float p = warp_sum(dot4(((const float4*)(wout + (long)VOC_BULK * EMB))[lane], uu));
        if (lane == 0) out[VOC_BULK] = p;
        m = p; d = 1.f;
    }
    if (lane == 0) { sm[wid] = m; sd[wid] = d; }
    __syncthreads();
    if (tid < 32) {
        float mm = (tid < WPB) ? sm[tid] : NEGBIG;
        float dd = (tid < WPB) ? sd[tid] : 0.f;
#pragma unroll
        for (int o = 4; o; o >>= 1) {
            float mo  = __shfl_xor_sync(0xFFFFFFFFu, mm, o);
            float ddo = __shfl_xor_sync(0xFFFFFFFFu, dd, o);
            float mn  = fmaxf(mm, mo);
            dd = dd * __expf(mm - mn) + ddo * __expf(mo - mn);
            mm = mn;
        }
        if (tid == 0) { g_plmax[blockIdx.x] = mm; g_plden[blockIdx.x] = dd; }
    }
    __threadfence();
    if (tid == 0) slast = (atomicAdd(&g_ctr_lg, 1u) == (unsigned)(gridDim.x - 1));
    __syncthreads();
    if (!slast) return;

    // ---- last block: block-parallel combine of partials, then normalize ----
    {
        float mm = NEGBIG, dd = 0.f;
        for (int b = tid; b < NB_LG; b += TBV) {   // <=4 per thread
            float mo = g_plmax[b], ddo = g_plden[b];
            float mn = fmaxf(mm, mo);
            dd = dd * __expf(mm - mn) + ddo * __expf(mo - mn);
            mm = mn;
        }
#pragma unroll
        for (int o = 16; o; o >>= 1) {
            float mo  = __shfl_xor_sync(0xFFFFFFFFu, mm, o);
            float ddo = __shfl_xor_sync(0xFFFFFFFFu, dd, o);
            float mn  = fmaxf(mm, mo);
            dd = dd * __expf(mm - mn) + ddo * __expf(mo - mn);
            mm = mn;
        }
        if (lane == 0) { smm[wid] = mm; sdm[wid] = dd; }
        __syncthreads();
        if (tid == 0) {
            float M = smm[0], D = sdm[0];
#pragma unroll
            for (int w2 = 1; w2 < TBV / 32; w2++) {
                float mn = fmaxf(M, smm[w2]);
                D = D * __expf(M - mn) + sdm[w2] * __expf(smm[w2] - mn);
                M = mn;
            }
            sc = M + logf(D);
            g_ctr_lg = 0u;
        }
    }
    __syncthreads();
    float c = sc;
    float4* o4 = (float4*)out;
    for (int i = tid; i < VOC_BULK / 4; i += TBV) {
        float4 v = o4[i];
        v.x -= c; v.y -= c; v.z -= c; v.w -= c;
        o4[i] = v;
    }
    if (tid == 0) out[VOC_BULK] -= c;
}

// ---------------- launch ----------------
extern "C" void kernel_launch(void* const* d_in, const int* in_sizes, int n_in,
                              void* d_out, int out_size) {
    const int*   query = (const int*)  d_in[0];
    const int*   story = (const int*)  d_in[1];
    const float* Wa    = (const float*)d_in[2];
    const float* Wc    = (const float*)d_in[3];
    const float* Wb    = (const float*)d_in[4];
    const float* Wt_w  = (const float*)d_in[5];
    const float* Wt_b  = (const float*)d_in[6];
    const float* H_w   = (const float*)d_in[7];
    const float* H_b   = (const float*)d_in[8];
    const float* wout  = (const float*)d_in[9];
    const float* TA    = (const float*)d_in[10];
    const float* TC    = (const float*)d_in[11];
    float* out = (float*)d_out;

    k_u0<<<1, EMB>>>(query, Wb);

    for (int h = 0; h < N_HOPS; h++) {
        k_pv    <<<NB_PV, TBV>>>(Wa, TA);
        k_hopmem<<<NBM, TBM>>>(story, TC);
        k_wo    <<<NB_WO, TBV>>>(Wc, Wt_w, Wt_b, H_w, H_b);
    }

    k_logits<<<NB_LG, TBV>>>(wout, out);
}

// round 11
// speedup vs baseline: 1.3546x; 1.2336x over previous
#include <cuda_runtime.h>
#include <math.h>

#define VOC      50257
#define VOC_BULK 50256           // divisible by 8
#define OCT_V    (VOC_BULK / 8)  // 6282 vocab row-octets
#define EMB      128
#define N_MEM    8192
#define OCT_M    (N_MEM / 8)     // 1024 memory row-octets
#define T_Q      50
#define T_M      50
#define N_HOPS   3

#define NBV  592                 // stream blocks (4/SM, one wave)
#define TBV  256
#define WPB  8
#define NWV  (NBV * WPB)         // 4736 warps

#define NBM  128                 // memory-space kernel: 128 x 256 = 1024 warps
#define TBM  256
#define MWARPS (NBM * (TBM / 32))

#define SHIFT 24.0f              // constant softmax shift (cancels exactly)
#define NEGBIG (-1e30f)

// ---------------- scratch ----------------
__device__ __align__(16) float g_u[EMB];
__device__ __align__(16) float g_pv[VOC + 8];
__device__ __align__(16) float g_sTA[N_MEM];
__device__ __align__(16) float g_cw[VOC + 8];
__device__ __align__(16) float g_wo[EMB];
__device__ float g_den;
__device__ float g_plmax[NBV];
__device__ float g_plden[NBV];

__device__ __forceinline__ float dot4(float4 a, float4 b) {
    return fmaf(a.x, b.x, fmaf(a.y, b.y, fmaf(a.z, b.z, a.w * b.w)));
}
__device__ __forceinline__ float warp_sum(float p) {
#pragma unroll
    for (int o = 16; o; o >>= 1) p += __shfl_xor_sync(0xFFFFFFFFu, p, o);
    return p;
}
__device__ __forceinline__ void oct_reduce(float* p) {
#pragma unroll
    for (int o = 16; o; o >>= 1) {
#pragma unroll
        for (int j = 0; j < 8; j++)
            p[j] += __shfl_xor_sync(0xFFFFFFFFu, p[j], o);
    }
}

// ---------------- u0 = sum_t Wb[query[t]] ----------------
__global__ void k_u0(const int* __restrict__ q, const float* __restrict__ Wb) {
    int e = threadIdx.x;
    float a = 0.f;
#pragma unroll 10
    for (int t = 0; t < T_Q; t++) a += Wb[(long)__ldg(q + t) * EMB + e];
    g_u[e] = a;
}

// ---------------- pv = Wa.u ; sTA = TA.u ; zero cw/wo/den (R8 body) ----------------
__global__ void __launch_bounds__(TBV) k_pv(const float* __restrict__ Wa,
                                            const float* __restrict__ TA) {
    __shared__ float4 su4[32];
    int tid = threadIdx.x, lane = tid & 31, wid = tid >> 5;
    int gid = blockIdx.x * TBV + tid;
    if (gid < VOC) g_cw[gid] = 0.f;
    if (blockIdx.x == 0) {
        if (tid < EMB) g_wo[tid] = 0.f;
        if (tid == EMB) g_den = 0.f;
    }
    if (tid < 32) su4[tid] = ((const float4*)g_u)[tid];
    __syncthreads();
    float4 uu = su4[lane];
    int gw = blockIdx.x * WPB + wid;

    for (int oc = gw; oc < OCT_V; oc += NWV) {
        const float4* a = (const float4*)(Wa + (long)oc * 8 * EMB);
        float4 v[8];
#pragma unroll
        for (int j = 0; j < 8; j++) v[j] = a[j * 32 + lane];
        float p[8];
#pragma unroll
        for (int j = 0; j < 8; j++) p[j] = dot4(v[j], uu);
        oct_reduce(p);
        if (lane == 0) {
            float4* dst = (float4*)(g_pv + oc * 8);
            dst[0] = make_float4(p[0], p[1], p[2], p[3]);
            dst[1] = make_float4(p[4], p[5], p[6], p[7]);
        }
    }
    for (int oc = gw; oc < OCT_M; oc += NWV) {
        const float4* a = (const float4*)(TA + (long)oc * 8 * EMB);
        float4 v[8];
#pragma unroll
        for (int j = 0; j < 8; j++) v[j] = a[j * 32 + lane];
        float p[8];
#pragma unroll
        for (int j = 0; j < 8; j++) p[j] = dot4(v[j], uu);
        oct_reduce(p);
        if (lane == 0) {
            float4* dst = (float4*)(g_sTA + oc * 8);
            dst[0] = make_float4(p[0], p[1], p[2], p[3]);
            dst[1] = make_float4(p[4], p[5], p[6], p[7]);
        }
    }
    if (gw == 0) {   // tail row
        float p = warp_sum(dot4(((const float4*)(Wa + (long)VOC_BULK * EMB))[lane], uu));
        if (lane == 0) g_pv[VOC_BULK] = p;
    }
}

// ---------------- hop memory phase: WARP PER MEMORY (lane-parallel gathers) ----------------
__global__ void __launch_bounds__(TBM) k_hopmem(const int* __restrict__ story,
                                                const float* __restrict__ TC) {
    __shared__ float sacc[TBM / 32][EMB];
    int tid = threadIdx.x, lane = tid & 31, wid = tid >> 5;
    int gw = blockIdx.x * (TBM / 32) + wid;

    float dloc = 0.f;
    float4 acc = make_float4(0.f, 0.f, 0.f, 0.f);
#pragma unroll
    for (int r = 0; r < N_MEM / MWARPS; r++) {
        int n = gw + r * MWARPS;
        const int* srow = story + (long)n * T_M;
        int tok0 = srow[lane];                          // lanes 0..31 -> tokens 0..31
        float sp = __ldg(g_pv + tok0);
        int tok1 = -1;
        if (lane < T_M - 32) {                          // lanes 0..17 -> tokens 32..49
            tok1 = srow[32 + lane];
            sp += __ldg(g_pv + tok1);
        }
        float s = warp_sum(sp) + g_sTA[n];
        float w = __expf(s - SHIFT);                    // identical on all lanes
        if (lane == 0) dloc += w;
        atomicAdd(&g_cw[tok0], w);
        if (tok1 >= 0) atomicAdd(&g_cw[tok1], w);
        float4 v = ((const float4*)(TC + (long)n * EMB))[lane];
        acc.x = fmaf(w, v.x, acc.x);
        acc.y = fmaf(w, v.y, acc.y);
        acc.z = fmaf(w, v.z, acc.z);
        acc.w = fmaf(w, v.w, acc.w);
    }
    if (lane == 0) atomicAdd(&g_den, dloc);
    sacc[wid][lane * 4 + 0] = acc.x;
    sacc[wid][lane * 4 + 1] = acc.y;
    sacc[wid][lane * 4 + 2] = acc.z;
    sacc[wid][lane * 4 + 3] = acc.w;
    __syncthreads();
    if (tid < EMB) {
        float v = 0.f;
#pragma unroll
        for (int w2 = 0; w2 < TBM / 32; w2++) v += sacc[w2][tid];
        atomicAdd(&g_wo[tid], v);
    }
}

// ---------------- wo += Wc^T.cw (R8 body) ----------------
__global__ void __launch_bounds__(TBV) k_wo(const float* __restrict__ Wc) {
    __shared__ float sacc[WPB][EMB];
    int tid = threadIdx.x, lane = tid & 31, wid = tid >> 5;
    int gw = blockIdx.x * WPB + wid;

    float4 acc = make_float4(0.f, 0.f, 0.f, 0.f);
    for (int oc = gw; oc < OCT_V; oc += NWV) {
        const float4* a = (const float4*)(Wc + (long)oc * 8 * EMB);
        float4 c4a = ((const float4*)g_cw)[oc * 2 + 0];
        float4 c4b = ((const float4*)g_cw)[oc * 2 + 1];
        float4 v[8];
#pragma unroll
        for (int j = 0; j < 8; j++) v[j] = a[j * 32 + lane];
        float c[8] = {c4a.x, c4a.y, c4a.z, c4a.w, c4b.x, c4b.y, c4b.z, c4b.w};
#pragma unroll
        for (int j = 0; j < 8; j++) {
            acc.x = fmaf(c[j], v[j].x, acc.x);
            acc.y = fmaf(c[j], v[j].y, acc.y);
            acc.z = fmaf(c[j], v[j].z, acc.z);
            acc.w = fmaf(c[j], v[j].w, acc.w);
        }
    }
    if (gw == 0) {   // tail row
        float c = g_cw[VOC_BULK];
        float4 v = ((const float4*)(Wc + (long)VOC_BULK * EMB))[lane];
        acc.x = fmaf(c, v.x, acc.x); acc.y = fmaf(c, v.y, acc.y);
        acc.z = fmaf(c, v.z, acc.z); acc.w = fmaf(c, v.w, acc.w);
    }
    sacc[wid][lane * 4 + 0] = acc.x;
    sacc[wid][lane * 4 + 1] = acc.y;
    sacc[wid][lane * 4 + 2] = acc.z;
    sacc[wid][lane * 4 + 3] = acc.w;
    __syncthreads();
    if (tid < EMB) {
        float v = 0.f;
#pragma unroll
        for (int w2 = 0; w2 < WPB; w2++) v += sacc[w2][tid];
        if (v != 0.f) atomicAdd(&g_wo[tid], v);
    }
}

// ---------------- gated update of u (8-row batched loads, MLP=8) ----------------
__global__ void k_update(const float* __restrict__ Wt_w, const float* __restrict__ Wt_b,
                         const float* __restrict__ H_w,  const float* __restrict__ H_b) {
    __shared__ __align__(16) float su[EMB], swo[EMB], sdd[2 * EMB];
    int tid = threadIdx.x, lane = tid & 31, wid = tid >> 5;
    if (tid < EMB) {
        su[tid]  = g_u[tid];
        swo[tid] = g_wo[tid] / g_den;
    }
    __syncthreads();
    {
        const float* W   = (wid < 4) ? Wt_w : H_w;            // uniform per warp
        const float* vec = (wid < 4) ? su : swo;
        float4 v4 = ((const float4*)vec)[lane];
        int base = (wid & 3) * 32;
#pragma unroll
        for (int r = 0; r < 4; r++) {
            int rr0 = base + r * 8;
            float4 w4[8];
#pragma unroll
            for (int j = 0; j < 8; j++)
                w4[j] = ((const float4*)(W + (long)(rr0 + j) * EMB))[lane];
            float p[8];
#pragma unroll
            for (int j = 0; j < 8; j++) p[j] = dot4(w4[j], v4);
            oct_reduce(p);
            if (lane < 8) sdd[((wid < 4) ? 0 : EMB) + rr0 + lane] = p[lane];
        }
    }
    __syncthreads();
    if (tid < EMB) {
        float t = 1.f / (1.f + __expf(-(sdd[tid] + Wt_b[tid])));
        g_u[tid] = su[tid] * (1.f - t) + (sdd[EMB + tid] + H_b[tid]) * t;
    }
}

// ---------------- logits + online partials (R8 body) ----------------
__global__ void __launch_bounds__(TBV) k_logits(const float* __restrict__ wout,
                                                float* __restrict__ out) {
    __shared__ float4 su4[32];
    __shared__ float sm[WPB], sd[WPB];
    int tid = threadIdx.x, lane = tid & 31, wid = tid >> 5;
    if (tid < 32) su4[tid] = ((const float4*)g_u)[tid];
    __syncthreads();
    float4 uu = su4[lane];
    int gw = blockIdx.x * WPB + wid;

    float m = NEGBIG, d = 0.f;
    if (gw == 0) {   // tail row
        float p = warp_sum(dot4(((const float4*)(wout + (long)VOC_BULK * EMB))[lane], uu));
        if (lane == 0) out[VOC_BULK] = p;
        m = p; d = 1.f;
    }
    for (int oc = gw; oc < OCT_V; oc += NWV) {
        const float4* a = (const float4*)(wout + (long)oc * 8 * EMB);
        float4 v[8];
#pragma unroll
        for (int j = 0; j < 8; j++) v[j] = a[j * 32 + lane];
        float p[8];
#pragma unroll
        for (int j = 0; j < 8; j++) p[j] = dot4(v[j], uu);
        oct_reduce(p);
        if (lane == 0) {
            float4* dst = (float4*)(out + oc * 8);
            dst[0] = make_float4(p[0], p[1], p[2], p[3]);
            dst[1] = make_float4(p[4], p[5], p[6], p[7]);
        }
        float mx = p[0];
#pragma unroll
        for (int j = 1; j < 8; j++) mx = fmaxf(mx, p[j]);
        float mn = fmaxf(m, mx);
        float dn = d * __expf(m - mn);
#pragma unroll
        for (int j = 0; j < 8; j++) dn += __expf(p[j] - mn);
        m = mn; d = dn;
    }
    if (lane == 0) { sm[wid] = m; sd[wid] = d; }
    __syncthreads();
    if (tid < 32) {
        float mm = (tid < WPB) ? sm[tid] : NEGBIG;
        float dd = (tid < WPB) ? sd[tid] : 0.f;
#pragma unroll
        for (int o = 4; o; o >>= 1) {
            float mo  = __shfl_xor_sync(0xFFFFFFFFu, mm, o);
            float ddo = __shfl_xor_sync(0xFFFFFFFFu, dd, o);
            float mn  = fmaxf(mm, mo);
            dd = dd * __expf(mm - mn) + ddo * __expf(mo - mn);
            mm = mn;
        }
        if (tid == 0) { g_plmax[blockIdx.x] = mm; g_plden[blockIdx.x] = dd; }
    }
}

// ---------------- combine partials + normalize ----------------
__global__ void k_norm(float* __restrict__ out) {
    __shared__ float sc;
    int tid = threadIdx.x, lane = tid & 31;
    if (tid < 32) {
        float mm = NEGBIG, dd = 0.f;
        for (int b = lane; b < NBV; b += 32) {
            float mo = g_plmax[b], ddo = g_plden[b];
            float mn = fmaxf(mm, mo);
            dd = dd * __expf(mm - mn) + ddo * __expf(mo - mn);
            mm = mn;
        }
#pragma unroll
        for (int o = 16; o; o >>= 1) {
            float mo  = __shfl_xor_sync(0xFFFFFFFFu, mm, o);
            float ddo = __shfl_xor_sync(0xFFFFFFFFu, dd, o);
            float mn  = fmaxf(mm, mo);
            dd = dd * __expf(mm - mn) + ddo * __expf(mo - mn);
            mm = mn;
        }
        if (tid == 0) sc = mm + logf(dd);
    }
    __syncthreads();
    float c = sc;
    float4* o4 = (float4*)out;
    for (int i = blockIdx.x * blockDim.x + tid; i < VOC_BULK / 4; i += gridDim.x * blockDim.x) {
        float4 v = o4[i];
        v.x -= c; v.y -= c; v.z -= c; v.w -= c;
        o4[i] = v;
    }
    if (blockIdx.x == 0 && tid == 0) out[VOC_BULK] -= c;
}

// ---------------- launch ----------------
extern "C" void kernel_launch(void* const* d_in, const int* in_sizes, int n_in,
                              void* d_out, int out_size) {
    const int*   query = (const int*)  d_in[0];
    const int*   story = (const int*)  d_in[1];
    const float* Wa    = (const float*)d_in[2];
    const float* Wc    = (const float*)d_in[3];
    const float* Wb    = (const float*)d_in[4];
    const float* Wt_w  = (const float*)d_in[5];
    const float* Wt_b  = (const float*)d_in[6];
    const float* H_w   = (const float*)d_in[7];
    const float* H_b   = (const float*)d_in[8];
    const float* wout  = (const float*)d_in[9];
    const float* TA    = (const float*)d_in[10];
    const float* TC    = (const float*)d_in[11];
    float* out = (float*)d_out;

    k_u0<<<1, EMB>>>(query, Wb);

    for (int h = 0; h < N_HOPS; h++) {
        k_pv    <<<NBV, TBV>>>(Wa, TA);
        k_hopmem<<<NBM, TBM>>>(story, TC);
        k_wo    <<<NBV, TBV>>>(Wc);
        k_update<<<1, 256>>>(Wt_w, Wt_b, H_w, H_b);
    }

    k_logits<<<NBV, TBV>>>(wout, out);
    k_norm  <<<148, 256>>>(out);
}

// round 12
// speedup vs baseline: 1.4567x; 1.0754x over previous
#include <cuda_runtime.h>
#include <math.h>

#define VOC      50257
#define VOC_BULK 50256           // divisible by 8
#define OCT_V    (VOC_BULK / 8)  // 6282 vocab row-octets
#define EMB      128
#define N_MEM    8192
#define OCT_M    (N_MEM / 8)     // 1024 memory row-octets
#define NTASK    (OCT_V + OCT_M + 1)   // unified pv task space (+1 tail row)
#define T_Q      50
#define T_M      50
#define N_HOPS   3

#define NBV  592                 // stream blocks (4/SM, one wave)
#define TBV  256
#define WPB  8
#define NWV  (NBV * WPB)         // 4736 warps

#define NBM  256                 // memory-space kernel: 256 x 256 = 2048 warps
#define TBM  256
#define MWARPS (NBM * (TBM / 32))

#define SHIFT 24.0f              // constant softmax shift (cancels exactly)
#define NEGBIG (-1e30f)

// ---------------- scratch ----------------
__device__ __align__(16) float g_u[EMB];
__device__ __align__(16) float g_pv[VOC + 8];
__device__ __align__(16) float g_sTA[N_MEM];
__device__ __align__(16) float g_cw[VOC + 8];
__device__ __align__(16) float g_wo[EMB];
__device__ float g_den;
__device__ float g_plmax[NBV];
__device__ float g_plden[NBV];

__device__ __forceinline__ float dot4(float4 a, float4 b) {
    return fmaf(a.x, b.x, fmaf(a.y, b.y, fmaf(a.z, b.z, a.w * b.w)));
}
__device__ __forceinline__ float warp_sum(float p) {
#pragma unroll
    for (int o = 16; o; o >>= 1) p += __shfl_xor_sync(0xFFFFFFFFu, p, o);
    return p;
}
__device__ __forceinline__ void oct_reduce(float* p) {
#pragma unroll
    for (int o = 16; o; o >>= 1) {
#pragma unroll
        for (int j = 0; j < 8; j++)
            p[j] += __shfl_xor_sync(0xFFFFFFFFu, p[j], o);
    }
}

// ---------------- pv = Wa.u ; sTA = TA.u ; zero cw/wo/den ; u0 prelude on hop 0 ----------------
__global__ void __launch_bounds__(TBV) k_pv(int hop,
                                            const float* __restrict__ Wa,
                                            const float* __restrict__ TA,
                                            const int* __restrict__ query,
                                            const float* __restrict__ Wb) {
    __shared__ __align__(16) float su[EMB];
    __shared__ int stok[T_Q];
    int tid = threadIdx.x, lane = tid & 31, wid = tid >> 5;

    int gid = blockIdx.x * TBV + tid;
    if (gid < VOC) g_cw[gid] = 0.f;
    if (blockIdx.x == 1) {
        if (tid < EMB) g_wo[tid] = 0.f;
        if (tid == EMB) g_den = 0.f;
    }

    if (hop == 0) {
        // redundant per-block u0 = sum_t Wb[query[t]] (50 independent gathers)
        if (tid < T_Q) stok[tid] = query[tid];
        __syncthreads();
        if (tid < EMB) {
            float a = 0.f;
#pragma unroll 10
            for (int t = 0; t < T_Q; t++) a += Wb[(long)stok[t] * EMB + tid];
            su[tid] = a;
            if (blockIdx.x == 0) g_u[tid] = a;     // for k_update's read
        }
    } else {
        if (tid < EMB) su[tid] = g_u[tid];
    }
    __syncthreads();
    float4 uu = ((const float4*)su)[lane];
    int gw = blockIdx.x * WPB + wid;

    // unified task space: [0, OCT_V) Wa octets, [OCT_V, OCT_V+OCT_M) TA octets, last = tail row
    for (int task = gw; task < NTASK; task += NWV) {
        if (task < OCT_V) {
            const float4* a = (const float4*)(Wa + (long)task * 8 * EMB);
            float4 v[8];
#pragma unroll
            for (int j = 0; j < 8; j++) v[j] = a[j * 32 + lane];
            float p[8];
#pragma unroll
            for (int j = 0; j < 8; j++) p[j] = dot4(v[j], uu);
            oct_reduce(p);
            if (lane == 0) {
                float4* dst = (float4*)(g_pv + task * 8);
                dst[0] = make_float4(p[0], p[1], p[2], p[3]);
                dst[1] = make_float4(p[4], p[5], p[6], p[7]);
            }
        } else if (task < OCT_V + OCT_M) {
            int oc = task - OCT_V;
            const float4* a = (const float4*)(TA + (long)oc * 8 * EMB);
            float4 v[8];
#pragma unroll
            for (int j = 0; j < 8; j++) v[j] = a[j * 32 + lane];
            float p[8];
#pragma unroll
            for (int j = 0; j < 8; j++) p[j] = dot4(v[j], uu);
            oct_reduce(p);
            if (lane == 0) {
                float4* dst = (float4*)(g_sTA + oc * 8);
                dst[0] = make_float4(p[0], p[1], p[2], p[3]);
                dst[1] = make_float4(p[4], p[5], p[6], p[7]);
            }
        } else {   // vocab tail row
            float p = warp_sum(dot4(((const float4*)(Wa + (long)VOC_BULK * EMB))[lane], uu));
            if (lane == 0) g_pv[VOC_BULK] = p;
        }
    }
}

// ---------------- hop memory phase: warp per memory (lane-parallel gathers) ----------------
__global__ void __launch_bounds__(TBM) k_hopmem(const int* __restrict__ story,
                                                const float* __restrict__ TC) {
    __shared__ float sacc[TBM / 32][EMB];
    int tid = threadIdx.x, lane = tid & 31, wid = tid >> 5;
    int gw = blockIdx.x * (TBM / 32) + wid;

    float dloc = 0.f;
    float4 acc = make_float4(0.f, 0.f, 0.f, 0.f);
#pragma unroll
    for (int r = 0; r < N_MEM / MWARPS; r++) {
        int n = gw + r * MWARPS;
        const int* srow = story + (long)n * T_M;
        int tok0 = srow[lane];                          // lanes 0..31 -> tokens 0..31
        float sp = __ldg(g_pv + tok0);
        int tok1 = -1;
        if (lane < T_M - 32) {                          // lanes 0..17 -> tokens 32..49
            tok1 = srow[32 + lane];
            sp += __ldg(g_pv + tok1);
        }
        float s = warp_sum(sp) + g_sTA[n];
        float w = __expf(s - SHIFT);                    // identical on all lanes
        if (lane == 0) dloc += w;
        atomicAdd(&g_cw[tok0], w);
        if (tok1 >= 0) atomicAdd(&g_cw[tok1], w);
        float4 v = ((const float4*)(TC + (long)n * EMB))[lane];
        acc.x = fmaf(w, v.x, acc.x);
        acc.y = fmaf(w, v.y, acc.y);
        acc.z = fmaf(w, v.z, acc.z);
        acc.w = fmaf(w, v.w, acc.w);
    }
    if (lane == 0) atomicAdd(&g_den, dloc);
    sacc[wid][lane * 4 + 0] = acc.x;
    sacc[wid][lane * 4 + 1] = acc.y;
    sacc[wid][lane * 4 + 2] = acc.z;
    sacc[wid][lane * 4 + 3] = acc.w;
    __syncthreads();
    if (tid < EMB) {
        float v = 0.f;
#pragma unroll
        for (int w2 = 0; w2 < TBM / 32; w2++) v += sacc[w2][tid];
        atomicAdd(&g_wo[tid], v);
    }
}

// ---------------- wo += Wc^T.cw (R8 body) ----------------
__global__ void __launch_bounds__(TBV) k_wo(const float* __restrict__ Wc) {
    __shared__ float sacc[WPB][EMB];
    int tid = threadIdx.x, lane = tid & 31, wid = tid >> 5;
    int gw = blockIdx.x * WPB + wid;

    float4 acc = make_float4(0.f, 0.f, 0.f, 0.f);
    for (int oc = gw; oc < OCT_V; oc += NWV) {
        const float4* a = (const float4*)(Wc + (long)oc * 8 * EMB);
        float4 c4a = ((const float4*)g_cw)[oc * 2 + 0];
        float4 c4b = ((const float4*)g_cw)[oc * 2 + 1];
        float4 v[8];
#pragma unroll
        for (int j = 0; j < 8; j++) v[j] = a[j * 32 + lane];
        float c[8] = {c4a.x, c4a.y, c4a.z, c4a.w, c4b.x, c4b.y, c4b.z, c4b.w};
#pragma unroll
        for (int j = 0; j < 8; j++) {
            acc.x = fmaf(c[j], v[j].x, acc.x);
            acc.y = fmaf(c[j], v[j].y, acc.y);
            acc.z = fmaf(c[j], v[j].z, acc.z);
            acc.w = fmaf(c[j], v[j].w, acc.w);
        }
    }
    if (gw == 0) {   // tail row
        float c = g_cw[VOC_BULK];
        float4 v = ((const float4*)(Wc + (long)VOC_BULK * EMB))[lane];
        acc.x = fmaf(c, v.x, acc.x); acc.y = fmaf(c, v.y, acc.y);
        acc.z = fmaf(c, v.z, acc.z); acc.w = fmaf(c, v.w, acc.w);
    }
    sacc[wid][lane * 4 + 0] = acc.x;
    sacc[wid][lane * 4 + 1] = acc.y;
    sacc[wid][lane * 4 + 2] = acc.z;
    sacc[wid][lane * 4 + 3] = acc.w;
    __syncthreads();
    if (tid < EMB) {
        float v = 0.f;
#pragma unroll
        for (int w2 = 0; w2 < WPB; w2++) v += sacc[w2][tid];
        if (v != 0.f) atomicAdd(&g_wo[tid], v);
    }
}

// ---------------- gated update of u (8-row batched loads, MLP=8) ----------------
__global__ void k_update(const float* __restrict__ Wt_w, const float* __restrict__ Wt_b,
                         const float* __restrict__ H_w,  const float* __restrict__ H_b) {
    __shared__ __align__(16) float su[EMB], swo[EMB], sdd[2 * EMB];
    int tid = threadIdx.x, lane = tid & 31, wid = tid >> 5;
    if (tid < EMB) {
        su[tid]  = g_u[tid];
        swo[tid] = g_wo[tid] / g_den;
    }
    __syncthreads();
    {
        const float* W   = (wid < 4) ? Wt_w : H_w;            // uniform per warp
        const float* vec = (wid < 4) ? su : swo;
        float4 v4 = ((const float4*)vec)[lane];
        int base = (wid & 3) * 32;
#pragma unroll
        for (int r = 0; r < 4; r++) {
            int rr0 = base + r * 8;
            float4 w4[8];
#pragma unroll
            for (int j = 0; j < 8; j++)
                w4[j] = ((const float4*)(W + (long)(rr0 + j) * EMB))[lane];
            float p[8];
#pragma unroll
            for (int j = 0; j < 8; j++) p[j] = dot4(w4[j], v4);
            oct_reduce(p);
            if (lane < 8) sdd[((wid < 4) ? 0 : EMB) + rr0 + lane] = p[lane];
        }
    }
    __syncthreads();
    if (tid < EMB) {
        float t = 1.f / (1.f + __expf(-(sdd[tid] + Wt_b[tid])));
        g_u[tid] = su[tid] * (1.f - t) + (sdd[EMB + tid] + H_b[tid]) * t;
    }
}

// ---------------- logits + online partials (R8 body) ----------------
__global__ void __launch_bounds__(TBV) k_logits(const float* __restrict__ wout,
                                                float* __restrict__ out) {
    __shared__ float4 su4[32];
    __shared__ float sm[WPB], sd[WPB];
    int tid = threadIdx.x, lane = tid & 31, wid = tid >> 5;
    if (tid < 32) su4[tid] = ((const float4*)g_u)[tid];
    __syncthreads();
    float4 uu = su4[lane];
    int gw = blockIdx.x * WPB + wid;

    float m = NEGBIG, d = 0.f;
    if (gw == 0) {   // tail row
        float p = warp_sum(dot4(((const float4*)(wout + (long)VOC_BULK * EMB))[lane], uu));
        if (lane == 0) out[VOC_BULK] = p;
        m = p; d = 1.f;
    }
    for (int oc = gw; oc < OCT_V; oc += NWV) {
        const float4* a = (const float4*)(wout + (long)oc * 8 * EMB);
        float4 v[8];
#pragma unroll
        for (int j = 0; j < 8; j++) v[j] = a[j * 32 + lane];
        float p[8];
#pragma unroll
        for (int j = 0; j < 8; j++) p[j] = dot4(v[j], uu);
        oct_reduce(p);
        if (lane == 0) {
            float4* dst = (float4*)(out + oc * 8);
            dst[0] = make_float4(p[0], p[1], p[2], p[3]);
            dst[1] = make_float4(p[4], p[5], p[6], p[7]);
        }
        float mx = p[0];
#pragma unroll
        for (int j = 1; j < 8; j++) mx = fmaxf(mx, p[j]);
        float mn = fmaxf(m, mx);
        float dn = d * __expf(m - mn);
#pragma unroll
        for (int j = 0; j < 8; j++) dn += __expf(p[j] - mn);
        m = mn; d = dn;
    }
    if (lane == 0) { sm[wid] = m; sd[wid] = d; }
    __syncthreads();
    if (tid < 32) {
        float mm = (tid < WPB) ? sm[tid] : NEGBIG;
        float dd = (tid < WPB) ? sd[tid] : 0.f;
#pragma unroll
        for (int o = 4; o; o >>= 1) {
            float mo  = __shfl_xor_sync(0xFFFFFFFFu, mm, o);
            float ddo = __shfl_xor_sync(0xFFFFFFFFu, dd, o);
            float mn  = fmaxf(mm, mo);
            dd = dd * __expf(mm - mn) + ddo * __expf(mo - mn);
            mm = mn;
        }
        if (tid == 0) { g_plmax[blockIdx.x] = mm; g_plden[blockIdx.x] = dd; }
    }
}

// ---------------- combine partials + normalize ----------------
__global__ void k_norm(float* __restrict__ out) {
    __shared__ float sc;
    int tid = threadIdx.x, lane = tid & 31;
    if (tid < 32) {
        float mm = NEGBIG, dd = 0.f;
        for (int b = lane; b < NBV; b += 32) {
            float mo = g_plmax[b], ddo = g_plden[b];
            float mn = fmaxf(mm, mo);
            dd = dd * __expf(mm - mn) + ddo * __expf(mo - mn);
            mm = mn;
        }
#pragma unroll
        for (int o = 16; o; o >>= 1) {
            float mo  = __shfl_xor_sync(0xFFFFFFFFu, mm, o);
            float ddo = __shfl_xor_sync(0xFFFFFFFFu, dd, o);
            float mn  = fmaxf(mm, mo);
            dd = dd * __expf(mm - mn) + ddo * __expf(mo - mn);
            mm = mn;
        }
        if (tid == 0) sc = mm + logf(dd);
    }
    __syncthreads();
    float c = sc;
    float4* o4 = (float4*)out;
    for (int i = blockIdx.x * blockDim.x + tid; i < VOC_BULK / 4; i += gridDim.x * blockDim.x) {
        float4 v = o4[i];
        v.x -= c; v.y -= c; v.z -= c; v.w -= c;
        o4[i] = v;
    }
    if (blockIdx.x == 0 && tid == 0) out[VOC_BULK] -= c;
}

// ---------------- launch ----------------
extern "C" void kernel_launch(void* const* d_in, const int* in_sizes, int n_in,
                              void* d_out, int out_size) {
    const int*   query = (const int*)  d_in[0];
    const int*   story = (const int*)  d_in[1];
    const float* Wa    = (const float*)d_in[2];
    const float* Wc    = (const float*)d_in[3];
    const float* Wb    = (const float*)d_in[4];
    const float* Wt_w  = (const float*)d_in[5];
    const float* Wt_b  = (const float*)d_in[6];
    const float* H_w   = (const float*)d_in[7];
    const float* H_b   = (const float*)d_in[8];
    const float* wout  = (const float*)d_in[9];
    const float* TA    = (const float*)d_in[10];
    const float* TC    = (const float*)d_in[11];
    float* out = (float*)d_out;

    for (int h = 0; h < N_HOPS; h++) {
        k_pv    <<<NBV, TBV>>>(h, Wa, TA, query, Wb);
        k_hopmem<<<NBM, TBM>>>(story, TC);
        k_wo    <<<NBV, TBV>>>(Wc);
        k_update<<<1, 256>>>(Wt_w, Wt_b, H_w, H_b);
    }

    k_logits<<<NBV, TBV>>>(wout, out);
    k_norm  <<<148, 256>>>(out);
}

// round 13
// speedup vs baseline: 1.5769x; 1.0825x over previous
#include <cuda_runtime.h>
#include <math.h>

#define VOC      50257
#define VOC_BULK 50256           // divisible by 8
#define OCT_V    (VOC_BULK / 8)  // 6282 vocab row-octets
#define EMB      128
#define N_MEM    8192
#define OCT_M    (N_MEM / 8)     // 1024 memory row-octets
#define OCT_W    (EMB / 8)       // 16 Wt_w row-octets
#define NTASK    (OCT_V + OCT_M + 1 + OCT_W)   // unified pv task space
#define T_Q      50
#define T_M      50
#define N_HOPS   3

#define NBV  592                 // stream blocks (4/SM, one wave)
#define TBV  256
#define WPB  8
#define NWV  (NBV * WPB)         // 4736 warps

#define NBM  256                 // memory-space kernel: 256 x 256 = 2048 warps
#define TBM  256
#define MWARPS (NBM * (TBM / 32))

#define SHIFT 24.0f              // constant softmax shift (cancels exactly)
#define NEGBIG (-1e30f)

// ---------------- scratch ----------------
__device__ __align__(16) float g_u[EMB];
__device__ __align__(16) float g_pv[VOC + 8];
__device__ __align__(16) float g_sTA[N_MEM];
__device__ __align__(16) float g_cw[VOC + 8];
__device__ __align__(16) float g_wo[EMB];
__device__ __align__(16) float g_dt[EMB];     // Wt_w . u (computed in k_pv)
__device__ float g_den;
__device__ float g_plmax[NBV];
__device__ float g_plden[NBV];

__device__ __forceinline__ float dot4(float4 a, float4 b) {
    return fmaf(a.x, b.x, fmaf(a.y, b.y, fmaf(a.z, b.z, a.w * b.w)));
}
__device__ __forceinline__ float warp_sum(float p) {
#pragma unroll
    for (int o = 16; o; o >>= 1) p += __shfl_xor_sync(0xFFFFFFFFu, p, o);
    return p;
}
__device__ __forceinline__ void oct_reduce(float* p) {
#pragma unroll
    for (int o = 16; o; o >>= 1) {
#pragma unroll
        for (int j = 0; j < 8; j++)
            p[j] += __shfl_xor_sync(0xFFFFFFFFu, p[j], o);
    }
}

// octet dot helper: 8 rows of W against uu, reduced across warp
__device__ __forceinline__ void oct_dot(const float* __restrict__ W, long row0,
                                        float4 uu, int lane, float* p) {
    const float4* a = (const float4*)(W + row0 * EMB);
    float4 v[8];
#pragma unroll
    for (int j = 0; j < 8; j++) v[j] = a[j * 32 + lane];
#pragma unroll
    for (int j = 0; j < 8; j++) p[j] = dot4(v[j], uu);
    oct_reduce(p);
}

// ---------------- pv = Wa.u ; sTA = TA.u ; dt = Wt_w.u ; zero cw/wo/den ; u0 on hop 0 ----------------
__global__ void __launch_bounds__(TBV) k_pv(int hop,
                                            const float* __restrict__ Wa,
                                            const float* __restrict__ TA,
                                            const float* __restrict__ Wt_w,
                                            const int* __restrict__ query,
                                            const float* __restrict__ Wb) {
    __shared__ __align__(16) float su[EMB];
    __shared__ int stok[T_Q];
    int tid = threadIdx.x, lane = tid & 31, wid = tid >> 5;

    int gid = blockIdx.x * TBV + tid;
    if (gid < VOC) g_cw[gid] = 0.f;
    if (blockIdx.x == 1) {
        if (tid < EMB) g_wo[tid] = 0.f;
        if (tid == EMB) g_den = 0.f;
    }

    if (hop == 0) {
        // redundant per-block u0 = sum_t Wb[query[t]]
        if (tid < T_Q) stok[tid] = query[tid];
        __syncthreads();
        if (tid < EMB) {
            float a = 0.f;
#pragma unroll 10
            for (int t = 0; t < T_Q; t++) a += Wb[(long)stok[t] * EMB + tid];
            su[tid] = a;
            if (blockIdx.x == 0) g_u[tid] = a;     // for k_update's read
        }
    } else {
        if (tid < EMB) su[tid] = g_u[tid];
    }
    __syncthreads();
    float4 uu = ((const float4*)su)[lane];
    int gw = blockIdx.x * WPB + wid;

    // tasks: [0,OCT_V) Wa ; [OCT_V,+OCT_M) TA ; +1 tail row ; [.., +OCT_W) Wt_w
    for (int task = gw; task < NTASK; task += NWV) {
        float p[8];
        if (task < OCT_V) {
            oct_dot(Wa, (long)task * 8, uu, lane, p);
            if (lane == 0) {
                float4* dst = (float4*)(g_pv + task * 8);
                dst[0] = make_float4(p[0], p[1], p[2], p[3]);
                dst[1] = make_float4(p[4], p[5], p[6], p[7]);
            }
        } else if (task < OCT_V + OCT_M) {
            int oc = task - OCT_V;
            oct_dot(TA, (long)oc * 8, uu, lane, p);
            if (lane == 0) {
                float4* dst = (float4*)(g_sTA + oc * 8);
                dst[0] = make_float4(p[0], p[1], p[2], p[3]);
                dst[1] = make_float4(p[4], p[5], p[6], p[7]);
            }
        } else if (task == OCT_V + OCT_M) {   // vocab tail row
            float pt = warp_sum(dot4(((const float4*)(Wa + (long)VOC_BULK * EMB))[lane], uu));
            if (lane == 0) g_pv[VOC_BULK] = pt;
        } else {                               // Wt_w octet -> g_dt
            int oc = task - (OCT_V + OCT_M + 1);
            oct_dot(Wt_w, (long)oc * 8, uu, lane, p);
            if (lane == 0) {
                float4* dst = (float4*)(g_dt + oc * 8);
                dst[0] = make_float4(p[0], p[1], p[2], p[3]);
                dst[1] = make_float4(p[4], p[5], p[6], p[7]);
            }
        }
    }
}

// ---------------- hop memory phase: warp per memory (lane-parallel gathers) ----------------
__global__ void __launch_bounds__(TBM) k_hopmem(const int* __restrict__ story,
                                                const float* __restrict__ TC) {
    __shared__ float sacc[TBM / 32][EMB];
    int tid = threadIdx.x, lane = tid & 31, wid = tid >> 5;
    int gw = blockIdx.x * (TBM / 32) + wid;

    float dloc = 0.f;
    float4 acc = make_float4(0.f, 0.f, 0.f, 0.f);
#pragma unroll
    for (int r = 0; r < N_MEM / MWARPS; r++) {
        int n = gw + r * MWARPS;
        const int* srow = story + (long)n * T_M;
        int tok0 = srow[lane];
        float sp = __ldg(g_pv + tok0);
        int tok1 = -1;
        if (lane < T_M - 32) {
            tok1 = srow[32 + lane];
            sp += __ldg(g_pv + tok1);
        }
        float s = warp_sum(sp) + g_sTA[n];
        float w = __expf(s - SHIFT);
        if (lane == 0) dloc += w;
        atomicAdd(&g_cw[tok0], w);
        if (tok1 >= 0) atomicAdd(&g_cw[tok1], w);
        float4 v = ((const float4*)(TC + (long)n * EMB))[lane];
        acc.x = fmaf(w, v.x, acc.x);
        acc.y = fmaf(w, v.y, acc.y);
        acc.z = fmaf(w, v.z, acc.z);
        acc.w = fmaf(w, v.w, acc.w);
    }
    if (lane == 0) atomicAdd(&g_den, dloc);
    sacc[wid][lane * 4 + 0] = acc.x;
    sacc[wid][lane * 4 + 1] = acc.y;
    sacc[wid][lane * 4 + 2] = acc.z;
    sacc[wid][lane * 4 + 3] = acc.w;
    __syncthreads();
    if (tid < EMB) {
        float v = 0.f;
#pragma unroll
        for (int w2 = 0; w2 < TBM / 32; w2++) v += sacc[w2][tid];
        atomicAdd(&g_wo[tid], v);
    }
}

// ---------------- wo += Wc^T.cw (R8 body) ----------------
__global__ void __launch_bounds__(TBV) k_wo(const float* __restrict__ Wc) {
    __shared__ float sacc[WPB][EMB];
    int tid = threadIdx.x, lane = tid & 31, wid = tid >> 5;
    int gw = blockIdx.x * WPB + wid;

    float4 acc = make_float4(0.f, 0.f, 0.f, 0.f);
    for (int oc = gw; oc < OCT_V; oc += NWV) {
        const float4* a = (const float4*)(Wc + (long)oc * 8 * EMB);
        float4 c4a = ((const float4*)g_cw)[oc * 2 + 0];
        float4 c4b = ((const float4*)g_cw)[oc * 2 + 1];
        float4 v[8];
#pragma unroll
        for (int j = 0; j < 8; j++) v[j] = a[j * 32 + lane];
        float c[8] = {c4a.x, c4a.y, c4a.z, c4a.w, c4b.x, c4b.y, c4b.z, c4b.w};
#pragma unroll
        for (int j = 0; j < 8; j++) {
            acc.x = fmaf(c[j], v[j].x, acc.x);
            acc.y = fmaf(c[j], v[j].y, acc.y);
            acc.z = fmaf(c[j], v[j].z, acc.z);
            acc.w = fmaf(c[j], v[j].w, acc.w);
        }
    }
    if (gw == 0) {   // tail row
        float c = g_cw[VOC_BULK];
        float4 v = ((const float4*)(Wc + (long)VOC_BULK * EMB))[lane];
        acc.x = fmaf(c, v.x, acc.x); acc.y = fmaf(c, v.y, acc.y);
        acc.z = fmaf(c, v.z, acc.z); acc.w = fmaf(c, v.w, acc.w);
    }
    sacc[wid][lane * 4 + 0] = acc.x;
    sacc[wid][lane * 4 + 1] = acc.y;
    sacc[wid][lane * 4 + 2] = acc.z;
    sacc[wid][lane * 4 + 3] = acc.w;
    __syncthreads();
    if (tid < EMB) {
        float v = 0.f;
#pragma unroll
        for (int w2 = 0; w2 < WPB; w2++) v += sacc[w2][tid];
        if (v != 0.f) atomicAdd(&g_wo[tid], v);
    }
}

// ---------------- gated update: dh = H_w.swo only (16 warps, 1 octet each) ----------------
__global__ void __launch_bounds__(512) k_update(const float* __restrict__ H_w,
                                                const float* __restrict__ Wt_b,
                                                const float* __restrict__ H_b) {
    __shared__ __align__(16) float swo[EMB], sdh[EMB];
    int tid = threadIdx.x, lane = tid & 31, wid = tid >> 5;
    if (tid < EMB) swo[tid] = g_wo[tid] / g_den;
    __syncthreads();

    {   // 16 warps x 1 octet = 128 rows of H_w
        float4 v4 = ((const float4*)swo)[lane];
        float p[8];
        oct_dot(H_w, (long)wid * 8, v4, lane, p);
        if (lane < 8) sdh[wid * 8 + lane] = p[lane];
    }
    __syncthreads();
    if (tid < EMB) {
        float t = 1.f / (1.f + __expf(-(g_dt[tid] + Wt_b[tid])));
        g_u[tid] = g_u[tid] * (1.f - t) + (sdh[tid] + H_b[tid]) * t;
    }
}

// ---------------- logits + online partials (R8 body) ----------------
__global__ void __launch_bounds__(TBV) k_logits(const float* __restrict__ wout,
                                                float* __restrict__ out) {
    __shared__ float4 su4[32];
    __shared__ float sm[WPB], sd[WPB];
    int tid = threadIdx.x, lane = tid & 31, wid = tid >> 5;
    if (tid < 32) su4[tid] = ((const float4*)g_u)[tid];
    __syncthreads();
    float4 uu = su4[lane];
    int gw = blockIdx.x * WPB + wid;

    float m = NEGBIG, d = 0.f;
    if (gw == 0) {   // tail row
        float p = warp_sum(dot4(((const float4*)(wout + (long)VOC_BULK * EMB))[lane], uu));
        if (lane == 0) out[VOC_BULK] = p;
        m = p; d = 1.f;
    }
    for (int oc = gw; oc < OCT_V; oc += NWV) {
        float p[8];
        oct_dot(wout, (long)oc * 8, uu, lane, p);
        if (lane == 0) {
            float4* dst = (float4*)(out + oc * 8);
            dst[0] = make_float4(p[0], p[1], p[2], p[3]);
            dst[1] = make_float4(p[4], p[5], p[6], p[7]);
        }
        float mx = p[0];
#pragma unroll
        for (int j = 1; j < 8; j++) mx = fmaxf(mx, p[j]);
        float mn = fmaxf(m, mx);
        float dn = d * __expf(m - mn);
#pragma unroll
        for (int j = 0; j < 8; j++) dn += __expf(p[j] - mn);
        m = mn; d = dn;
    }
    if (lane == 0) { sm[wid] = m; sd[wid] = d; }
    __syncthreads();
    if (tid < 32) {
        float mm = (tid < WPB) ? sm[tid] : NEGBIG;
        float dd = (tid < WPB) ? sd[tid] : 0.f;
#pragma unroll
        for (int o = 4; o; o >>= 1) {
            float mo  = __shfl_xor_sync(0xFFFFFFFFu, mm, o);
            float ddo = __shfl_xor_sync(0xFFFFFFFFu, dd, o);
            float mn  = fmaxf(mm, mo);
            dd = dd * __expf(mm - mn) + ddo * __expf(mo - mn);
            mm = mn;
        }
        if (tid == 0) { g_plmax[blockIdx.x] = mm; g_plden[blockIdx.x] = dd; }
    }
}

// ---------------- combine partials + normalize ----------------
__global__ void k_norm(float* __restrict__ out) {
    __shared__ float sc;
    int tid = threadIdx.x, lane = tid & 31;
    if (tid < 32) {
        float mm = NEGBIG, dd = 0.f;
        for (int b = lane; b < NBV; b += 32) {
            float mo = g_plmax[b], ddo = g_plden[b];
            float mn = fmaxf(mm, mo);
            dd = dd * __expf(mm - mn) + ddo * __expf(mo - mn);
            mm = mn;
        }
#pragma unroll
        for (int o = 16; o; o >>= 1) {
            float mo  = __shfl_xor_sync(0xFFFFFFFFu, mm, o);
            float ddo = __shfl_xor_sync(0xFFFFFFFFu, dd, o);
            float mn  = fmaxf(mm, mo);
            dd = dd * __expf(mm - mn) + ddo * __expf(mo - mn);
            mm = mn;
        }
        if (tid == 0) sc = mm + logf(dd);
    }
    __syncthreads();
    float c = sc;
    float4* o4 = (float4*)out;
    for (int i = blockIdx.x * blockDim.x + tid; i < VOC_BULK / 4; i += gridDim.x * blockDim.x) {
        float4 v = o4[i];
        v.x -= c; v.y -= c; v.z -= c; v.w -= c;
        o4[i] = v;
    }
    if (blockIdx.x == 0 && tid == 0) out[VOC_BULK] -= c;
}

// ---------------- launch ----------------
extern "C" void kernel_launch(void* const* d_in, const int* in_sizes, int n_in,
                              void* d_out, int out_size) {
    const int*   query = (const int*)  d_in[0];
    const int*   story = (const int*)  d_in[1];
    const float* Wa    = (const float*)d_in[2];
    const float* Wc    = (const float*)d_in[3];
    const float* Wb    = (const float*)d_in[4];
    const float* Wt_w  = (const float*)d_in[5];
    const float* Wt_b  = (const float*)d_in[6];
    const float* H_w   = (const float*)d_in[7];
    const float* H_b   = (const float*)d_in[8];
    const float* wout  = (const float*)d_in[9];
    const float* TA    = (const float*)d_in[10];
    const float* TC    = (const float*)d_in[11];
    float* out = (float*)d_out;

    for (int h = 0; h < N_HOPS; h++) {
        k_pv    <<<NBV, TBV>>>(h, Wa, TA, Wt_w, query, Wb);
        k_hopmem<<<NBM, TBM>>>(story, TC);
        k_wo    <<<NBV, TBV>>>(Wc);
        k_update<<<1, 512>>>(H_w, Wt_b, H_b);
    }

    k_logits<<<NBV, TBV>>>(wout, out);
    k_norm  <<<148, 256>>>(out);
}

// round 14
// speedup vs baseline: 1.6272x; 1.0319x over previous
#include <cuda_runtime.h>
#include <math.h>

#define VOC      50257
#define VOC_BULK 50256           // divisible by 8
#define OCT_V    (VOC_BULK / 8)  // 6282 vocab row-octets
#define EMB      128
#define N_MEM    8192
#define OCT_M    (N_MEM / 8)     // 1024 memory row-octets
#define OCT_W    (EMB / 8)       // 16 Wt_w row-octets
#define NTASK    (OCT_V + OCT_M + 1 + OCT_W)   // unified pv task space
#define T_Q      50
#define T_M      50
#define N_HOPS   3

#define NBV  592                 // stream blocks (4/SM, one wave)
#define TBV  256
#define WPB  8
#define NWV  (NBV * WPB)         // 4736 warps

#define NBM  256                 // memory-space kernel: 256 x 256 = 2048 warps
#define TBM  256
#define MWARPS (NBM * (TBM / 32))

#define SHIFT 24.0f              // constant softmax shift (cancels exactly)
#define NEGBIG (-1e30f)

// ---------------- scratch ----------------
__device__ __align__(16) float g_uarr[N_HOPS][EMB];   // u after hop-h prelude gate
__device__ __align__(16) float g_pv[VOC + 8];
__device__ __align__(16) float g_sTA[N_MEM];
__device__ __align__(16) float g_cw[VOC + 8];
__device__ __align__(16) float g_wo[EMB];
__device__ __align__(16) float g_dt[2][EMB];          // Wt_w . u, parity-buffered
__device__ __align__(16) float g_dh[EMB];             // H_w . swo
__device__ float g_den;
__device__ float g_plmax[NBV];
__device__ float g_plden[NBV];

__device__ __forceinline__ float dot4(float4 a, float4 b) {
    return fmaf(a.x, b.x, fmaf(a.y, b.y, fmaf(a.z, b.z, a.w * b.w)));
}
__device__ __forceinline__ float warp_sum(float p) {
#pragma unroll
    for (int o = 16; o; o >>= 1) p += __shfl_xor_sync(0xFFFFFFFFu, p, o);
    return p;
}
__device__ __forceinline__ void oct_reduce(float* p) {
#pragma unroll
    for (int o = 16; o; o >>= 1) {
#pragma unroll
        for (int j = 0; j < 8; j++)
            p[j] += __shfl_xor_sync(0xFFFFFFFFu, p[j], o);
    }
}
__device__ __forceinline__ void oct_dot(const float* __restrict__ W, long row0,
                                        float4 uu, int lane, float* p) {
    const float4* a = (const float4*)(W + row0 * EMB);
    float4 v[8];
#pragma unroll
    for (int j = 0; j < 8; j++) v[j] = a[j * 32 + lane];
#pragma unroll
    for (int j = 0; j < 8; j++) p[j] = dot4(v[j], uu);
    oct_reduce(p);
}

// redundant elementwise gate: u_h = u_{h-1}*(1-t) + (dh+H_b)*t, t = sigmoid(dt+Wt_b)
__device__ __forceinline__ float gate_elem(int hop, int e,
                                           const float* __restrict__ Wt_b,
                                           const float* __restrict__ H_b) {
    float t = 1.f / (1.f + __expf(-(g_dt[(hop - 1) & 1][e] + Wt_b[e])));
    return g_uarr[hop - 1][e] * (1.f - t) + (g_dh[e] + H_b[e]) * t;
}

// ---------------- pv = Wa.u ; sTA = TA.u ; dt = Wt_w.u ; gate prelude ; zero scratch ----------------
__global__ void __launch_bounds__(TBV) k_pv(int hop,
                                            const float* __restrict__ Wa,
                                            const float* __restrict__ TA,
                                            const float* __restrict__ Wt_w,
                                            const int* __restrict__ query,
                                            const float* __restrict__ Wb,
                                            const float* __restrict__ Wt_b,
                                            const float* __restrict__ H_b) {
    __shared__ __align__(16) float su[EMB];
    __shared__ int stok[T_Q];
    int tid = threadIdx.x, lane = tid & 31, wid = tid >> 5;

    int gid = blockIdx.x * TBV + tid;
    if (gid < VOC) g_cw[gid] = 0.f;
    if (blockIdx.x == 1) {
        if (tid < EMB) g_wo[tid] = 0.f;
        if (tid == EMB) g_den = 0.f;
    }

    if (hop == 0) {
        // redundant per-block u0 = sum_t Wb[query[t]]
        if (tid < T_Q) stok[tid] = query[tid];
        __syncthreads();
        if (tid < EMB) {
            float a = 0.f;
#pragma unroll 10
            for (int t = 0; t < T_Q; t++) a += Wb[(long)stok[t] * EMB + tid];
            su[tid] = a;
            if (blockIdx.x == 0) g_uarr[0][tid] = a;
        }
    } else {
        if (tid < EMB) {
            float un = gate_elem(hop, tid, Wt_b, H_b);
            su[tid] = un;
            if (blockIdx.x == 0) g_uarr[hop][tid] = un;
        }
    }
    __syncthreads();
    float4 uu = ((const float4*)su)[lane];
    int gw = blockIdx.x * WPB + wid;

    // tasks: [0,OCT_V) Wa ; [OCT_V,+OCT_M) TA ; +1 tail row ; [.., +OCT_W) Wt_w
    for (int task = gw; task < NTASK; task += NWV) {
        float p[8];
        if (task < OCT_V) {
            oct_dot(Wa, (long)task * 8, uu, lane, p);
            if (lane == 0) {
                float4* dst = (float4*)(g_pv + task * 8);
                dst[0] = make_float4(p[0], p[1], p[2], p[3]);
                dst[1] = make_float4(p[4], p[5], p[6], p[7]);
            }
        } else if (task < OCT_V + OCT_M) {
            int oc = task - OCT_V;
            oct_dot(TA, (long)oc * 8, uu, lane, p);
            if (lane == 0) {
                float4* dst = (float4*)(g_sTA + oc * 8);
                dst[0] = make_float4(p[0], p[1], p[2], p[3]);
                dst[1] = make_float4(p[4], p[5], p[6], p[7]);
            }
        } else if (task == OCT_V + OCT_M) {   // vocab tail row
            float pt = warp_sum(dot4(((const float4*)(Wa + (long)VOC_BULK * EMB))[lane], uu));
            if (lane == 0) g_pv[VOC_BULK] = pt;
        } else {                               // Wt_w octet -> g_dt[hop parity]
            int oc = task - (OCT_V + OCT_M + 1);
            oct_dot(Wt_w, (long)oc * 8, uu, lane, p);
            if (lane == 0) {
                float4* dst = (float4*)(g_dt[hop & 1] + oc * 8);
                dst[0] = make_float4(p[0], p[1], p[2], p[3]);
                dst[1] = make_float4(p[4], p[5], p[6], p[7]);
            }
        }
    }
}

// ---------------- hop memory phase: warp per memory (lane-parallel gathers) ----------------
__global__ void __launch_bounds__(TBM) k_hopmem(const int* __restrict__ story,
                                                const float* __restrict__ TC) {
    __shared__ float sacc[TBM / 32][EMB];
    int tid = threadIdx.x, lane = tid & 31, wid = tid >> 5;
    int gw = blockIdx.x * (TBM / 32) + wid;

    float dloc = 0.f;
    float4 acc = make_float4(0.f, 0.f, 0.f, 0.f);
#pragma unroll
    for (int r = 0; r < N_MEM / MWARPS; r++) {
        int n = gw + r * MWARPS;
        const int* srow = story + (long)n * T_M;
        int tok0 = srow[lane];
        float sp = __ldg(g_pv + tok0);
        int tok1 = -1;
        if (lane < T_M - 32) {
            tok1 = srow[32 + lane];
            sp += __ldg(g_pv + tok1);
        }
        float s = warp_sum(sp) + g_sTA[n];
        float w = __expf(s - SHIFT);
        if (lane == 0) dloc += w;
        atomicAdd(&g_cw[tok0], w);
        if (tok1 >= 0) atomicAdd(&g_cw[tok1], w);
        float4 v = ((const float4*)(TC + (long)n * EMB))[lane];
        acc.x = fmaf(w, v.x, acc.x);
        acc.y = fmaf(w, v.y, acc.y);
        acc.z = fmaf(w, v.z, acc.z);
        acc.w = fmaf(w, v.w, acc.w);
    }
    if (lane == 0) atomicAdd(&g_den, dloc);
    sacc[wid][lane * 4 + 0] = acc.x;
    sacc[wid][lane * 4 + 1] = acc.y;
    sacc[wid][lane * 4 + 2] = acc.z;
    sacc[wid][lane * 4 + 3] = acc.w;
    __syncthreads();
    if (tid < EMB) {
        float v = 0.f;
#pragma unroll
        for (int w2 = 0; w2 < TBM / 32; w2++) v += sacc[w2][tid];
        atomicAdd(&g_wo[tid], v);
    }
}

// ---------------- wo += Wc^T.cw (R8 body) ----------------
__global__ void __launch_bounds__(TBV) k_wo(const float* __restrict__ Wc) {
    __shared__ float sacc[WPB][EMB];
    int tid = threadIdx.x, lane = tid & 31, wid = tid >> 5;
    int gw = blockIdx.x * WPB + wid;

    float4 acc = make_float4(0.f, 0.f, 0.f, 0.f);
    for (int oc = gw; oc < OCT_V; oc += NWV) {
        const float4* a = (const float4*)(Wc + (long)oc * 8 * EMB);
        float4 c4a = ((const float4*)g_cw)[oc * 2 + 0];
        float4 c4b = ((const float4*)g_cw)[oc * 2 + 1];
        float4 v[8];
#pragma unroll
        for (int j = 0; j < 8; j++) v[j] = a[j * 32 + lane];
        float c[8] = {c4a.x, c4a.y, c4a.z, c4a.w, c4b.x, c4b.y, c4b.z, c4b.w};
#pragma unroll
        for (int j = 0; j < 8; j++) {
            acc.x = fmaf(c[j], v[j].x, acc.x);
            acc.y = fmaf(c[j], v[j].y, acc.y);
            acc.z = fmaf(c[j], v[j].z, acc.z);
            acc.w = fmaf(c[j], v[j].w, acc.w);
        }
    }
    if (gw == 0) {   // tail row
        float c = g_cw[VOC_BULK];
        float4 v = ((const float4*)(Wc + (long)VOC_BULK * EMB))[lane];
        acc.x = fmaf(c, v.x, acc.x); acc.y = fmaf(c, v.y, acc.y);
        acc.z = fmaf(c, v.z, acc.z); acc.w = fmaf(c, v.w, acc.w);
    }
    sacc[wid][lane * 4 + 0] = acc.x;
    sacc[wid][lane * 4 + 1] = acc.y;
    sacc[wid][lane * 4 + 2] = acc.z;
    sacc[wid][lane * 4 + 3] = acc.w;
    __syncthreads();
    if (tid < EMB) {
        float v = 0.f;
#pragma unroll
        for (int w2 = 0; w2 < WPB; w2++) v += sacc[w2][tid];
        if (v != 0.f) atomicAdd(&g_wo[tid], v);
    }
}

// ---------------- dh = H_w . (wo/den): 16 blocks x 8 warps = warp per row ----------------
__global__ void __launch_bounds__(256) k_dh(const float* __restrict__ H_w) {
    int tid = threadIdx.x, lane = tid & 31, wid = tid >> 5;
    int row = blockIdx.x * 8 + wid;                     // 16*8 = 128 rows
    float4 wo4 = make_float4(g_wo[lane * 4 + 0], g_wo[lane * 4 + 1],
                             g_wo[lane * 4 + 2], g_wo[lane * 4 + 3]);
    float inv = 1.f / g_den;
    wo4.x *= inv; wo4.y *= inv; wo4.z *= inv; wo4.w *= inv;
    float p = warp_sum(dot4(((const float4*)(H_w + (long)row * EMB))[lane], wo4));
    if (lane == 0) g_dh[row] = p;
}

// ---------------- logits + online partials (gate prelude) ----------------
__global__ void __launch_bounds__(TBV) k_logits(const float* __restrict__ wout,
                                                const float* __restrict__ Wt_b,
                                                const float* __restrict__ H_b,
                                                float* __restrict__ out) {
    __shared__ __align__(16) float su[EMB];
    __shared__ float sm[WPB], sd[WPB];
    int tid = threadIdx.x, lane = tid & 31, wid = tid >> 5;
    if (tid < EMB) su[tid] = gate_elem(N_HOPS, tid, Wt_b, H_b);   // parity (N_HOPS-1)&1
    __syncthreads();
    float4 uu = ((const float4*)su)[lane];
    int gw = blockIdx.x * WPB + wid;

    float m = NEGBIG, d = 0.f;
    if (gw == 0) {   // tail row
        float p = warp_sum(dot4(((const float4*)(wout + (long)VOC_BULK * EMB))[lane], uu));
        if (lane == 0) out[VOC_BULK] = p;
        m = p; d = 1.f;
    }
    for (int oc = gw; oc < OCT_V; oc += NWV) {
        float p[8];
        oct_dot(wout, (long)oc * 8, uu, lane, p);
        if (lane == 0) {
            float4* dst = (float4*)(out + oc * 8);
            dst[0] = make_float4(p[0], p[1], p[2], p[3]);
            dst[1] = make_float4(p[4], p[5], p[6], p[7]);
        }
        float mx = p[0];
#pragma unroll
        for (int j = 1; j < 8; j++) mx = fmaxf(mx, p[j]);
        float mn = fmaxf(m, mx);
        float dn = d * __expf(m - mn);
#pragma unroll
        for (int j = 0; j < 8; j++) dn += __expf(p[j] - mn);
        m = mn; d = dn;
    }
    if (lane == 0) { sm[wid] = m; sd[wid] = d; }
    __syncthreads();
    if (tid < 32) {
        float mm = (tid < WPB) ? sm[tid] : NEGBIG;
        float dd = (tid < WPB) ? sd[tid] : 0.f;
#pragma unroll
        for (int o = 4; o; o >>= 1) {
            float mo  = __shfl_xor_sync(0xFFFFFFFFu, mm, o);
            float ddo = __shfl_xor_sync(0xFFFFFFFFu, dd, o);
            float mn  = fmaxf(mm, mo);
            dd = dd * __expf(mm - mn) + ddo * __expf(mo - mn);
            mm = mn;
        }
        if (tid == 0) { g_plmax[blockIdx.x] = mm; g_plden[blockIdx.x] = dd; }
    }
}

// ---------------- combine partials + normalize ----------------
__global__ void k_norm(float* __restrict__ out) {
    __shared__ float sc;
    int tid = threadIdx.x, lane = tid & 31;
    if (tid < 32) {
        float mm = NEGBIG, dd = 0.f;
        for (int b = lane; b < NBV; b += 32) {
            float mo = g_plmax[b], ddo = g_plden[b];
            float mn = fmaxf(mm, mo);
            dd = dd * __expf(mm - mn) + ddo * __expf(mo - mn);
            mm = mn;
        }
#pragma unroll
        for (int o = 16; o; o >>= 1) {
            float mo  = __shfl_xor_sync(0xFFFFFFFFu, mm, o);
            float ddo = __shfl_xor_sync(0xFFFFFFFFu, dd, o);
            float mn  = fmaxf(mm, mo);
            dd = dd * __expf(mm - mn) + ddo * __expf(mo - mn);
            mm = mn;
        }
        if (tid == 0) sc = mm + logf(dd);
    }
    __syncthreads();
    float c = sc;
    float4* o4 = (float4*)out;
    for (int i = blockIdx.x * blockDim.x + tid; i < VOC_BULK / 4; i += gridDim.x * blockDim.x) {
        float4 v = o4[i];
        v.x -= c; v.y -= c; v.z -= c; v.w -= c;
        o4[i] = v;
    }
    if (blockIdx.x == 0 && tid == 0) out[VOC_BULK] -= c;
}

// ---------------- launch ----------------
extern "C" void kernel_launch(void* const* d_in, const int* in_sizes, int n_in,
                              void* d_out, int out_size) {
    const int*   query = (const int*)  d_in[0];
    const int*   story = (const int*)  d_in[1];
    const float* Wa    = (const float*)d_in[2];
    const float* Wc    = (const float*)d_in[3];
    const float* Wb    = (const float*)d_in[4];
    const float* Wt_w  = (const float*)d_in[5];
    const float* Wt_b  = (const float*)d_in[6];
    const float* H_w   = (const float*)d_in[7];
    const float* H_b   = (const float*)d_in[8];
    const float* wout  = (const float*)d_in[9];
    const float* TA    = (const float*)d_in[10];
    const float* TC    = (const float*)d_in[11];
    float* out = (float*)d_out;

    for (int h = 0; h < N_HOPS; h++) {
        k_pv    <<<NBV, TBV>>>(h, Wa, TA, Wt_w, query, Wb, Wt_b, H_b);
        k_hopmem<<<NBM, TBM>>>(story, TC);
        k_wo    <<<NBV, TBV>>>(Wc);
        k_dh    <<<16, 256>>>(H_w);
    }

    k_logits<<<NBV, TBV>>>(wout, Wt_b, H_b, out);
    k_norm  <<<148, 256>>>(out);
}